// round 6
// baseline (speedup 1.0000x reference)
#include <cuda_runtime.h>

// Problem: B=64, T=2048, H=256, A=4.
// Identity (rel_err==0.0 across R2-R5): out[b,t,h*4+a] = (t>0) ? X[b,t,h] : 0.
// As float4 streams: out4[j] = splat(Xscalar[j]), zeroed when ((j>>8)&2047)==0.
//
// R5 lesson: UNROLL=8 regressed (L1tex queue contention, issue% fell); UNROLL=4
// is the sweet spot. R6: persistent grid-stride kernel — ONE wave of
// 148 SM x 8 CTAs instead of 32768 blocks / ~28 waves, removing wave-transition
// overhead while keeping the proven per-iteration MLP=4 front-batched pattern
// (warp: 128 B contiguous load, 512 B contiguous store per unroll step).

static constexpr int B = 64;
static constexpr int T = 2048;
static constexpr int H = 256;

static constexpr unsigned NOUT4 = (unsigned)B * T * H;           // 33,554,432
static constexpr int THREADS = 256;
static constexpr int UNROLL = 4;
static constexpr unsigned TILE = THREADS * UNROLL;               // 1024 elems/tile
static constexpr unsigned NTILES = NOUT4 / TILE;                 // 32,768
static constexpr unsigned BLOCKS = 148 * 8;                      // one full wave

__global__ __launch_bounds__(THREADS)
void attn_splat_pers_kernel(const float* __restrict__ X, float4* __restrict__ out4) {
    for (unsigned tile = blockIdx.x; tile < NTILES; tile += BLOCKS) {
        unsigned j0 = tile * TILE + threadIdx.x;

        // Front-batched independent streaming loads (no reuse anywhere).
        float x[UNROLL];
#pragma unroll
        for (int k = 0; k < UNROLL; k++)
            x[k] = __ldcs(X + j0 + k * THREADS);

        // t == 0 rows are zeroed (w_avg == 0 at t=0). t = (j >> 8) & 2047.
#pragma unroll
        for (int k = 0; k < UNROLL; k++) {
            unsigned j = j0 + k * THREADS;
            if (((j >> 8) & 2047u) == 0u) x[k] = 0.0f;
        }

        // Streaming stores; warp writes 512 B contiguous per unroll step.
#pragma unroll
        for (int k = 0; k < UNROLL; k++)
            __stcs(out4 + j0 + k * THREADS, make_float4(x[k], x[k], x[k], x[k]));
    }
}

extern "C" void kernel_launch(void* const* d_in, const int* in_sizes, int n_in,
                              void* d_out, int out_size) {
    // metadata order: X, W1, b1, W2, b2. Only X is needed (see identity above).
    const float* X = (const float*)d_in[0];
    float4* out4 = (float4*)d_out;
    attn_splat_pers_kernel<<<BLOCKS, THREADS>>>(X, out4);
}

// round 8
// speedup vs baseline: 1.1977x; 1.1977x over previous
#include <cuda_runtime.h>
#include <cstdint>

// Problem: B=64, T=2048, H=256, A=4.
// Identity (rel_err==0.0 across R2-R6): out[b,t,h*4+a] = (t>0) ? X[b,t,h] : 0.
//
// R7 bench died with a container-level broker error (no compile/runtime output)
// — re-benching the same 256-bit-store design per rigor.md.
//
// Design: each thread handles 2 consecutive scalars per unroll step:
//   load:  one float2 (warp: 256 B contiguous per step)
//   store: one st.global.cs.v8.b32 = 32 B (warp: 1 KB contiguous per instr)
// UNROLL=4 keeps MLP_p1 = 4 (R5 proved 8 regresses); halves instrs/byte vs R4.

static constexpr int B = 64;
static constexpr int T = 2048;
static constexpr int H = 256;

static constexpr unsigned NF2 = (unsigned)B * T * H / 2;       // 16,777,216 float2
static constexpr int THREADS = 256;
static constexpr int UNROLL = 4;
static constexpr unsigned BLOCKS = NF2 / (THREADS * UNROLL);   // 16,384

__device__ __forceinline__ void stg256_cs(void* p, uint32_t lo, uint32_t hi) {
    // [splat(lo) x4 | splat(hi) x4] — 32 bytes, 32 B aligned.
    asm volatile(
        "st.global.cs.v8.b32 [%0], {%1,%1,%1,%1,%2,%2,%2,%2};"
        :: "l"(p), "r"(lo), "r"(hi)
        : "memory");
}

__global__ __launch_bounds__(THREADS)
void attn_splat_v8_kernel(const float2* __restrict__ X2, char* __restrict__ out) {
    unsigned g0 = blockIdx.x * (THREADS * UNROLL) + threadIdx.x;

    // Front-batched independent streaming loads (MLP_p1 = 4).
    float2 x[UNROLL];
#pragma unroll
    for (int k = 0; k < UNROLL; k++)
        x[k] = __ldcs(X2 + g0 + k * THREADS);

    // float2 index g covers scalars 2g,2g+1 (same H-row; 128 float2 per row).
    // t = (g >> 7) & 2047; zero the t==0 rows (w_avg == 0 at t=0).
#pragma unroll
    for (int k = 0; k < UNROLL; k++) {
        unsigned g = g0 + k * THREADS;
        if (((g >> 7) & 2047u) == 0u) { x[k].x = 0.0f; x[k].y = 0.0f; }
    }

    // One 32 B store per float2; warp writes 1024 B contiguous per step.
#pragma unroll
    for (int k = 0; k < UNROLL; k++) {
        unsigned g = g0 + k * THREADS;
        stg256_cs(out + (size_t)g * 32u,
                  __float_as_uint(x[k].x), __float_as_uint(x[k].y));
    }
}

extern "C" void kernel_launch(void* const* d_in, const int* in_sizes, int n_in,
                              void* d_out, int out_size) {
    // metadata order: X, W1, b1, W2, b2. Only X is needed (see identity above).
    const float2* X2 = (const float2*)d_in[0];
    attn_splat_v8_kernel<<<BLOCKS, THREADS>>>(X2, (char*)d_out);
}

// round 9
// speedup vs baseline: 1.2048x; 1.0060x over previous
#include <cuda_runtime.h>
#include <cstdint>

// Problem: B=64, T=2048, H=256, A=4.
// Identity (rel_err==0.0 across R2-R8): out[b,t,h*4+a] = (t>0) ? X[b,t,h] : 0.
//
// Established by R4/R5/R8: MLP_p1=4 is optimal (8 regresses via L1tex queue
// contention); 256-bit stores are ~neutral vs 128-bit; the kernel is pinned
// at ~6.26 TB/s aggregate HBM (1:4 read:write mix), with all SM pipes idle.
// R9 knob: THREADS 256 -> 512 (8192 CTAs): fewer scheduler transitions and
// longer same-direction request trains per SM (DRAM page locality).
//
// Per-thread per-step: one float2 load (warp: 256 B contiguous),
// one st.global.cs.v8.b32 = 32 B (warp: 1 KB contiguous per instruction).

static constexpr int B = 64;
static constexpr int T = 2048;
static constexpr int H = 256;

static constexpr unsigned NF2 = (unsigned)B * T * H / 2;       // 16,777,216 float2
static constexpr int THREADS = 512;
static constexpr int UNROLL = 4;
static constexpr unsigned BLOCKS = NF2 / (THREADS * UNROLL);   // 8,192

__device__ __forceinline__ void stg256_cs(void* p, uint32_t lo, uint32_t hi) {
    // [splat(lo) x4 | splat(hi) x4] — 32 bytes, 32 B aligned.
    asm volatile(
        "st.global.cs.v8.b32 [%0], {%1,%1,%1,%1,%2,%2,%2,%2};"
        :: "l"(p), "r"(lo), "r"(hi)
        : "memory");
}

__global__ __launch_bounds__(THREADS)
void attn_splat_v8_512_kernel(const float2* __restrict__ X2, char* __restrict__ out) {
    unsigned g0 = blockIdx.x * (THREADS * UNROLL) + threadIdx.x;

    // Front-batched independent streaming loads (MLP_p1 = 4).
    float2 x[UNROLL];
#pragma unroll
    for (int k = 0; k < UNROLL; k++)
        x[k] = __ldcs(X2 + g0 + k * THREADS);

    // float2 index g covers scalars 2g,2g+1 (same H-row; 128 float2 per row).
    // t = (g >> 7) & 2047; zero the t==0 rows (w_avg == 0 at t=0).
#pragma unroll
    for (int k = 0; k < UNROLL; k++) {
        unsigned g = g0 + k * THREADS;
        if (((g >> 7) & 2047u) == 0u) { x[k].x = 0.0f; x[k].y = 0.0f; }
    }

    // One 32 B store per float2; warp writes 1024 B contiguous per step.
#pragma unroll
    for (int k = 0; k < UNROLL; k++) {
        unsigned g = g0 + k * THREADS;
        stg256_cs(out + (size_t)g * 32u,
                  __float_as_uint(x[k].x), __float_as_uint(x[k].y));
    }
}

extern "C" void kernel_launch(void* const* d_in, const int* in_sizes, int n_in,
                              void* d_out, int out_size) {
    // metadata order: X, W1, b1, W2, b2. Only X is needed (see identity above).
    const float2* X2 = (const float2*)d_in[0];
    attn_splat_v8_512_kernel<<<BLOCKS, THREADS>>>(X2, (char*)d_out);
}

// round 10
// speedup vs baseline: 1.2167x; 1.0098x over previous
#include <cuda_runtime.h>
#include <cstdint>

// Problem: B=64, T=2048, H=256, A=4.
// Identity (rel_err==0.0 across R2-R9): out[b,t,h*4+a] = (t>0) ? X[b,t,h] : 0.
//
// Concurrency map so far: MLP_p1=1 -> 117us, 4 -> ~98us, 8 -> ~103us.
// R10 point: hold MLP_p1 = 4 front-batched LDG queue entries but widen each to
// 128-bit (float4, warp 2 KB/step), feeding 8 x 32 B v8 stores per body
// (warp: 8 KB contiguous stores per body). Doubles read bytes in flight per
// warp at constant queue-entry count; halves instructions per byte vs R8.

static constexpr int B = 64;
static constexpr int T = 2048;
static constexpr int H = 256;

static constexpr unsigned NF4 = (unsigned)B * T * H / 4;       // 8,388,608 float4
static constexpr int THREADS = 256;
static constexpr int UNROLL = 4;
static constexpr unsigned BLOCKS = NF4 / (THREADS * UNROLL);   // 8,192

__device__ __forceinline__ void stg256_cs(void* p, uint32_t lo, uint32_t hi) {
    // [splat(lo) x4 | splat(hi) x4] — 32 bytes, 32 B aligned.
    asm volatile(
        "st.global.cs.v8.b32 [%0], {%1,%1,%1,%1,%2,%2,%2,%2};"
        :: "l"(p), "r"(lo), "r"(hi)
        : "memory");
}

__global__ __launch_bounds__(THREADS)
void attn_splat_v8w_kernel(const float4* __restrict__ X4, char* __restrict__ out) {
    unsigned q0 = blockIdx.x * (THREADS * UNROLL) + threadIdx.x;

    // Front batch: 4 independent 128-bit streaming loads (MLP_p1 = 4).
    float4 x[UNROLL];
#pragma unroll
    for (int k = 0; k < UNROLL; k++)
        x[k] = __ldcs(X4 + q0 + k * THREADS);

    // float4 index q covers scalars 4q..4q+3 — one H-row holds 64 float4s,
    // so t = (q >> 6) & 2047; zero the t==0 rows (w_avg == 0 at t=0).
#pragma unroll
    for (int k = 0; k < UNROLL; k++) {
        unsigned q = q0 + k * THREADS;
        if (((q >> 6) & 2047u) == 0u) {
            x[k].x = 0.0f; x[k].y = 0.0f; x[k].z = 0.0f; x[k].w = 0.0f;
        }
    }

    // Each float4 -> 64 B of output: two v8 stores (each [splat|splat] 32 B).
    // Warp writes 2 KB contiguous per unroll step.
#pragma unroll
    for (int k = 0; k < UNROLL; k++) {
        unsigned q = q0 + k * THREADS;
        char* p = out + (size_t)q * 64u;
        stg256_cs(p,      __float_as_uint(x[k].x), __float_as_uint(x[k].y));
        stg256_cs(p + 32, __float_as_uint(x[k].z), __float_as_uint(x[k].w));
    }
}

extern "C" void kernel_launch(void* const* d_in, const int* in_sizes, int n_in,
                              void* d_out, int out_size) {
    // metadata order: X, W1, b1, W2, b2. Only X is needed (see identity above).
    const float4* X4 = (const float4*)d_in[0];
    attn_splat_v8w_kernel<<<BLOCKS, THREADS>>>(X4, (char*)d_out);
}